// round 4
// baseline (speedup 1.0000x reference)
#include <cuda_runtime.h>
#include <cuda_bf16.h>
#include <math.h>
#include <stdint.h>

#define NBATCH 32
#define SLEN   2048
#define NIN    128
#define HSZ    256
#define G4     1024
#define NTOK   (NBATCH * SLEN)   // 65536
#define QDIM   16
#define MMEM   64

// ---------------- static scratch (allocation-free) ----------------
__device__ float g_xg[(size_t)NTOK * G4];   // xg for the current layer
__device__ float g_h [(size_t)NTOK * HSZ];  // h1, then lstm_out
__device__ float g_mv[MMEM * HSZ];          // mem_vals @ Wq^T
__device__ float g_w [NTOK * 4];            // per-token scaled top3 weights
__device__ int   g_idx[NTOK * 4];           // per-token top3 indices

// =================================================================
// Tiled SIMT GEMM: C[m,n] = sum_k A[m,k]*B[n,k] + bias1[n] + bias2[n]
// BM=BN=64, BK=16, 256 threads, 4x4 per thread.
// Requires M,N multiples of 64 and K multiple of 16 (all true here).
// =================================================================
__global__ __launch_bounds__(256) void gemm_bt_kernel(
    const float* __restrict__ A, int lda,
    const float* __restrict__ B, int ldb,
    float* __restrict__ C, int ldc,
    int K,
    const float* __restrict__ bias1, const float* __restrict__ bias2)
{
    __shared__ __align__(16) float As[16][68];
    __shared__ __align__(16) float Bs[16][68];
    int tid = threadIdx.x;
    int bm = blockIdx.y * 64, bn = blockIdx.x * 64;
    int lr = tid >> 2, lk = (tid & 3) * 4;
    int tx = tid & 15, ty = tid >> 4;
    float acc[4][4] = {};
    const float* Ap = A + (size_t)(bm + lr) * lda + lk;
    const float* Bp = B + (size_t)(bn + lr) * ldb + lk;

    for (int k0 = 0; k0 < K; k0 += 16) {
        float4 av = *(const float4*)(Ap + k0);
        float4 bv = *(const float4*)(Bp + k0);
        As[lk + 0][lr] = av.x; As[lk + 1][lr] = av.y;
        As[lk + 2][lr] = av.z; As[lk + 3][lr] = av.w;
        Bs[lk + 0][lr] = bv.x; Bs[lk + 1][lr] = bv.y;
        Bs[lk + 2][lr] = bv.z; Bs[lk + 3][lr] = bv.w;
        __syncthreads();
#pragma unroll
        for (int kk = 0; kk < 16; kk++) {
            float4 a4 = *(const float4*)&As[kk][ty * 4];
            float4 b4 = *(const float4*)&Bs[kk][tx * 4];
            float a[4] = {a4.x, a4.y, a4.z, a4.w};
            float b[4] = {b4.x, b4.y, b4.z, b4.w};
#pragma unroll
            for (int i = 0; i < 4; i++)
#pragma unroll
                for (int j = 0; j < 4; j++)
                    acc[i][j] = fmaf(a[i], b[j], acc[i][j]);
        }
        __syncthreads();
    }

    float bcol[4];
#pragma unroll
    for (int j = 0; j < 4; j++) {
        int n = bn + tx * 4 + j;
        float bv = 0.f;
        if (bias1) bv += bias1[n];
        if (bias2) bv += bias2[n];
        bcol[j] = bv;
    }
#pragma unroll
    for (int i = 0; i < 4; i++) {
        int m = bm + ty * 4 + i;
        float4 o;
        o.x = acc[i][0] + bcol[0];
        o.y = acc[i][1] + bcol[1];
        o.z = acc[i][2] + bcol[2];
        o.w = acc[i][3] + bcol[3];
        *(float4*)&C[(size_t)m * ldc + bn + tx * 4] = o;
    }
}

// =================================================================
// Output GEMM with fused quantum-memory epilogue:
//   out[m,n] = cw * (lstm[m,:] . Wc[n,:]) + b_out[n]
//            + sum_{k<3} w[m,k] * MV[idx[m,k]][n]
// Wc = W_out[:, :256] accessed with ldb=512.
// =================================================================
__global__ __launch_bounds__(256) void out_gemm_kernel(
    const float* __restrict__ A, int lda,
    const float* __restrict__ B, int ldb,
    float* __restrict__ C, int ldc,
    int K,
    const float* __restrict__ bout,
    const float* __restrict__ cwp,
    const float* __restrict__ wts,
    const int*   __restrict__ idxs,
    const float* __restrict__ MV)
{
    __shared__ __align__(16) float As[16][68];
    __shared__ __align__(16) float Bs[16][68];
    int tid = threadIdx.x;
    int bm = blockIdx.y * 64, bn = blockIdx.x * 64;
    int lr = tid >> 2, lk = (tid & 3) * 4;
    int tx = tid & 15, ty = tid >> 4;
    float acc[4][4] = {};
    const float* Ap = A + (size_t)(bm + lr) * lda + lk;
    const float* Bp = B + (size_t)(bn + lr) * ldb + lk;

    for (int k0 = 0; k0 < K; k0 += 16) {
        float4 av = *(const float4*)(Ap + k0);
        float4 bv = *(const float4*)(Bp + k0);
        As[lk + 0][lr] = av.x; As[lk + 1][lr] = av.y;
        As[lk + 2][lr] = av.z; As[lk + 3][lr] = av.w;
        Bs[lk + 0][lr] = bv.x; Bs[lk + 1][lr] = bv.y;
        Bs[lk + 2][lr] = bv.z; Bs[lk + 3][lr] = bv.w;
        __syncthreads();
#pragma unroll
        for (int kk = 0; kk < 16; kk++) {
            float4 a4 = *(const float4*)&As[kk][ty * 4];
            float4 b4 = *(const float4*)&Bs[kk][tx * 4];
            float a[4] = {a4.x, a4.y, a4.z, a4.w};
            float b[4] = {b4.x, b4.y, b4.z, b4.w};
#pragma unroll
            for (int i = 0; i < 4; i++)
#pragma unroll
                for (int j = 0; j < 4; j++)
                    acc[i][j] = fmaf(a[i], b[j], acc[i][j]);
        }
        __syncthreads();
    }

    float cw = *cwp;
#pragma unroll
    for (int i = 0; i < 4; i++) {
        int m = bm + ty * 4 + i;
        float w0 = wts[m * 4 + 0], w1 = wts[m * 4 + 1], w2 = wts[m * 4 + 2];
        int   i0 = idxs[m * 4 + 0], i1 = idxs[m * 4 + 1], i2 = idxs[m * 4 + 2];
        const float* mv0 = MV + (size_t)i0 * HSZ;
        const float* mv1 = MV + (size_t)i1 * HSZ;
        const float* mv2 = MV + (size_t)i2 * HSZ;
        float out4[4];
#pragma unroll
        for (int j = 0; j < 4; j++) {
            int n = bn + tx * 4 + j;
            float v = cw * acc[i][j] + bout[n];
            v = fmaf(w0, mv0[n], v);
            v = fmaf(w1, mv1[n], v);
            v = fmaf(w2, mv2[n], v);
            out4[j] = v;
        }
        *(float4*)&C[(size_t)m * ldc + bn + tx * 4] =
            make_float4(out4[0], out4[1], out4[2], out4[3]);
    }
}

// =================================================================
// MV[m][h] = sum_h' mem_vals[m][h'] * W_out[h][256 + h']
// =================================================================
__global__ void mv_kernel(const float* __restrict__ vals,
                          const float* __restrict__ Wout,
                          float* __restrict__ mv)
{
    int m = blockIdx.x, h = threadIdx.x;
    const float* vrow = vals + (size_t)m * HSZ;
    const float* wrow = Wout + (size_t)h * 2 * HSZ + HSZ;
    float acc = 0.f;
#pragma unroll 8
    for (int k = 0; k < HSZ; k++) acc = fmaf(vrow[k], wrow[k], acc);
    mv[(size_t)m * HSZ + h] = acc;
}

// =================================================================
// LSTM scan: 16 clusters x 8 CTAs, 2 batch rows per cluster.
// CTA `crank` owns h-columns [crank*32, crank*32+32) => 128 gate rows,
// whose W_hh slice lives in registers as packed f32x2 pairs.
// h is exchanged via st.shared::cluster + one barrier.cluster per step.
// =================================================================
__device__ __forceinline__ unsigned mapa_u32(unsigned addr, unsigned rank) {
    unsigned r;
    asm("mapa.shared::cluster.u32 %0, %1, %2;" : "=r"(r) : "r"(addr), "r"(rank));
    return r;
}
__device__ __forceinline__ void st_cluster_f32(unsigned addr, float v) {
    asm volatile("st.shared::cluster.f32 [%0], %1;" :: "r"(addr), "f"(v) : "memory");
}
__device__ __forceinline__ void cluster_sync_all() {
    asm volatile("barrier.cluster.arrive.aligned;" ::: "memory");
    asm volatile("barrier.cluster.wait.aligned;" ::: "memory");
}
__device__ __forceinline__ void ffma2(unsigned long long& acc,
                                      unsigned long long a,
                                      unsigned long long b) {
    asm("fma.rn.f32x2 %0, %1, %2, %3;" : "=l"(acc) : "l"(a), "l"(b), "l"(acc));
}
__device__ __forceinline__ float f2lo(unsigned long long v) {
    return __uint_as_float((unsigned)(v & 0xffffffffull));
}
__device__ __forceinline__ float f2hi(unsigned long long v) {
    return __uint_as_float((unsigned)(v >> 32));
}

__global__ __launch_bounds__(256, 1) __cluster_dims__(8, 1, 1)
void lstm_scan_kernel(const float* __restrict__ xg,    // [32][2048][1024]
                      const float* __restrict__ Whh,   // [1024][256]
                      float* __restrict__ hout)        // [32][2048][256]
{
    // hbuf[parity][batch][k], gbuf[batch][local gate row]
    __shared__ __align__(16) float hbuf[2][2][HSZ];
    __shared__ float gbuf[2][128];

    int tid = threadIdx.x;
    int crank = blockIdx.x & 7;
    int cid   = blockIdx.x >> 3;
    int b0 = cid * 2;
    int lr = tid >> 1;           // local gate row in [0,128)
    int kc = tid & 1;            // k half: [kc*128, kc*128+128)
    int grow = (lr >> 5) * HSZ + crank * 32 + (lr & 31);

    // Pack W_hh slice into 64 f32x2 registers per thread
    unsigned long long w2[64];
    {
        const unsigned long long* wp =
            (const unsigned long long*)(Whh + (size_t)grow * HSZ + kc * 128);
#pragma unroll
        for (int i = 0; i < 64; i++) w2[i] = wp[i];
    }

    unsigned hb0 = (unsigned)__cvta_generic_to_shared(&hbuf[0][0][0]);
    unsigned peer[8];
#pragma unroll
    for (int p = 0; p < 8; p++) peer[p] = mapa_u32(hb0, (unsigned)p);

    for (int i = tid; i < 2 * 2 * HSZ; i += 256) ((float*)hbuf)[i] = 0.f;

    // pointwise roles: 64 threads = 2 batches x 32 columns
    bool pw = tid < 64;
    int pb = tid >> 5, pj = tid & 31;
    float c_state = 0.f;
    float x0 = 0.f, x1 = 0.f, x2 = 0.f, x3 = 0.f;
    const float* xgb = xg;
    float* hob = hout;
    if (pw) {
        xgb = xg + (size_t)(b0 + pb) * SLEN * G4 + crank * 32 + pj;
        hob = hout + (size_t)(b0 + pb) * SLEN * HSZ + crank * 32 + pj;
        x0 = xgb[0]; x1 = xgb[256]; x2 = xgb[512]; x3 = xgb[768];
    }
    __syncthreads();
    cluster_sync_all();   // all hbufs zeroed before anyone pushes

    for (int t = 0; t < SLEN; t++) {
        int par = t & 1;
        const ulonglong2* hA = (const ulonglong2*)&hbuf[par][0][kc * 128];
        const ulonglong2* hB = (const ulonglong2*)&hbuf[par][1][kc * 128];
        unsigned long long a0 = 0ull, a1 = 0ull, c0 = 0ull, c1 = 0ull;
#pragma unroll
        for (int i = 0; i < 32; i++) {
            ulonglong2 va = hA[i];
            ulonglong2 vb = hB[i];
            ffma2(a0, w2[2 * i + 0], va.x);
            ffma2(a1, w2[2 * i + 1], va.y);
            ffma2(c0, w2[2 * i + 0], vb.x);
            ffma2(c1, w2[2 * i + 1], vb.y);
        }
        float sa = (f2lo(a0) + f2hi(a0)) + (f2lo(a1) + f2hi(a1));
        float sb = (f2lo(c0) + f2hi(c0)) + (f2lo(c1) + f2hi(c1));
        sa += __shfl_xor_sync(0xffffffffu, sa, 1);
        sb += __shfl_xor_sync(0xffffffffu, sb, 1);
        if (kc == 0) { gbuf[0][lr] = sa; gbuf[1][lr] = sb; }
        __syncthreads();

        if (pw) {
            float gi = gbuf[pb][      pj] + x0;
            float gf = gbuf[pb][ 32 + pj] + x1;
            float gg = gbuf[pb][ 64 + pj] + x2;
            float go = gbuf[pb][ 96 + pj] + x3;
            float si = 1.f / (1.f + expf(-gi));
            float sf = 1.f / (1.f + expf(-gf));
            float so = 1.f / (1.f + expf(-go));
            float tg = tanhf(gg);
            c_state = sf * c_state + si * tg;
            float h = so * tanhf(c_state);
            hob[(size_t)t * HSZ] = h;
            unsigned off = (unsigned)((((par ^ 1) * 2 + pb) * HSZ +
                                       crank * 32 + pj) * 4);
#pragma unroll
            for (int p = 0; p < 8; p++) st_cluster_f32(peer[p] + off, h);
            int tn = (t + 1 < SLEN) ? (t + 1) : t;
            const float* xp = xgb + (size_t)tn * G4;
            x0 = xp[0]; x1 = xp[256]; x2 = xp[512]; x3 = xp[768];
        }
        cluster_sync_all();
    }
}

// =================================================================
// kNN over quantum memory: per token -> 3 indices + 3 scaled weights
// =================================================================
__global__ __launch_bounds__(256) void knn_kernel(
    const float* __restrict__ lstm,
    const float* __restrict__ Wcq, const float* __restrict__ bcq,
    const float* __restrict__ keys, const float* __restrict__ qwp,
    float* __restrict__ wout, int* __restrict__ idxout)
{
    __shared__ float sWcq[QDIM][HSZ];
    __shared__ float skn[MMEM][QDIM];
    __shared__ __align__(16) float sh[8][HSZ];
    __shared__ float sq[8][QDIM];
    __shared__ float ssims[8][MMEM];
    int tid = threadIdx.x;
    for (int i = tid; i < QDIM * HSZ; i += 256)
        sWcq[i >> 8][i & 255] = Wcq[i];
    if (tid < MMEM) {
        float kv[QDIM]; float nrm = 0.f;
#pragma unroll
        for (int d = 0; d < QDIM; d++) { kv[d] = keys[tid * QDIM + d]; nrm += kv[d] * kv[d]; }
        float inv = 1.f / (sqrtf(nrm) + 1e-8f);
#pragma unroll
        for (int d = 0; d < QDIM; d++) skn[tid][d] = kv[d] * inv;
    }
    __syncthreads();

    int wid = tid >> 5, lane = tid & 31;
    int token = blockIdx.x * 8 + wid;
    const float* hrow = lstm + (size_t)token * HSZ;
    for (int i = lane; i < HSZ / 4; i += 32)
        ((float4*)sh[wid])[i] = ((const float4*)hrow)[i];
    __syncwarp();
    if (lane < QDIM) {
        float acc = bcq[lane];
#pragma unroll 8
        for (int k = 0; k < HSZ; k++) acc = fmaf(sWcq[lane][k], sh[wid][k], acc);
        sq[wid][lane] = tanhf(acc);
    }
    __syncwarp();
    float qn[QDIM];
    {
        float nrm = 0.f;
#pragma unroll
        for (int d = 0; d < QDIM; d++) { float v = sq[wid][d]; nrm += v * v; }
        float inv = 1.f / (sqrtf(nrm) + 1e-8f);
#pragma unroll
        for (int d = 0; d < QDIM; d++) qn[d] = sq[wid][d] * inv;
    }
#pragma unroll
    for (int mm = 0; mm < 2; mm++) {
        int m = lane + mm * 32;
        float s = 0.f;
#pragma unroll
        for (int d = 0; d < QDIM; d++) s = fmaf(qn[d], skn[m][d], s);
        ssims[wid][m] = s;
    }
    __syncwarp();
    if (lane == 0) {
        float v0 = -1e30f, v1 = -1e30f, v2 = -1e30f;
        int i0 = 0, i1 = 0, i2 = 0;
        for (int m = 0; m < MMEM; m++) {
            float s = ssims[wid][m];
            if (s > v0)      { v2 = v1; i2 = i1; v1 = v0; i1 = i0; v0 = s; i0 = m; }
            else if (s > v1) { v2 = v1; i2 = i1; v1 = s;  i1 = m; }
            else if (s > v2) { v2 = s;  i2 = m; }
        }
        float tot = v0 + v1 + v2;
        float qw = *qwp;
        float sc = (tot > 0.f) ? (qw / tot) : 0.f;
        wout[token * 4 + 0] = v0 * sc;
        wout[token * 4 + 1] = v1 * sc;
        wout[token * 4 + 2] = v2 * sc;
        idxout[token * 4 + 0] = i0;
        idxout[token * 4 + 1] = i1;
        idxout[token * 4 + 2] = i2;
    }
}

// =================================================================
extern "C" void kernel_launch(void* const* d_in, const int* in_sizes, int n_in,
                              void* d_out, int out_size) {
    const float* x      = (const float*)d_in[0];
    const float* W_ih0  = (const float*)d_in[1];
    const float* W_hh0  = (const float*)d_in[2];
    const float* b_ih0  = (const float*)d_in[3];
    const float* b_hh0  = (const float*)d_in[4];
    const float* W_ih1  = (const float*)d_in[5];
    const float* W_hh1  = (const float*)d_in[6];
    const float* b_ih1  = (const float*)d_in[7];
    const float* b_hh1  = (const float*)d_in[8];
    const float* W_cq   = (const float*)d_in[9];
    const float* b_cq   = (const float*)d_in[10];
    const float* mkeys  = (const float*)d_in[11];
    const float* mvals  = (const float*)d_in[12];
    const float* W_out  = (const float*)d_in[13];
    const float* b_out  = (const float*)d_in[14];
    const float* cw     = (const float*)d_in[15];
    const float* qw     = (const float*)d_in[16];
    float* out = (float*)d_out;

    float* xg  = nullptr; cudaGetSymbolAddress((void**)&xg,  g_xg);
    float* hbf = nullptr; cudaGetSymbolAddress((void**)&hbf, g_h);
    float* mv  = nullptr; cudaGetSymbolAddress((void**)&mv,  g_mv);
    float* wts = nullptr; cudaGetSymbolAddress((void**)&wts, g_w);
    int*   idx = nullptr; cudaGetSymbolAddress((void**)&idx, g_idx);

    // MV = mem_vals @ Wq^T (independent, tiny)
    mv_kernel<<<MMEM, HSZ>>>(mvals, W_out, mv);

    // layer 0: xg0 = x @ W_ih0^T + b_ih0 + b_hh0, then scan
    {
        dim3 grid(G4 / 64, NTOK / 64);
        gemm_bt_kernel<<<grid, 256>>>(x, NIN, W_ih0, NIN, xg, G4, NIN,
                                      b_ih0, b_hh0);
    }
    lstm_scan_kernel<<<128, 256>>>(xg, W_hh0, hbf);

    // layer 1: xg1 = h1 @ W_ih1^T + b_ih1 + b_hh1, then scan
    {
        dim3 grid(G4 / 64, NTOK / 64);
        gemm_bt_kernel<<<grid, 256>>>(hbf, HSZ, W_ih1, HSZ, xg, G4, HSZ,
                                      b_ih1, b_hh1);
    }
    lstm_scan_kernel<<<128, 256>>>(xg, W_hh1, hbf);

    // kNN epilogue metadata
    knn_kernel<<<NTOK / 8, 256>>>(hbf, W_cq, b_cq, mkeys, qw, wts, idx);

    // out = cw*(lstm@Wc^T) + b_out + sum_k w_k*MV[idx_k]
    {
        dim3 grid(HSZ / 64, NTOK / 64);
        out_gemm_kernel<<<grid, 256>>>(hbf, HSZ, W_out, 2 * HSZ, out, HSZ, HSZ,
                                       b_out, cw, wts, idx, mv);
    }
}